// round 12
// baseline (speedup 1.0000x reference)
#include <cuda_runtime.h>
#include <cuda_fp16.h>
#include <stdint.h>

// Problem constants
#define F_I     512
#define F_O     32
#define F_NCH   32                 // i-chunks of 16
#define F_WROWS 32                 // rows per warp (4 n-tiles of 8)
#define F_THR   128                // 4 warps -> 128 rows per CTA

// W packed in exact mma A-fragment order:
//   g_Wf[ ((c*8 + ks)*2 + oT)*32 + lane ] = uint4{a0,a1,a2,a3}
//   A[rr][kk] = fp16( W[i = c*16+kk][o = oT*16+rr][j = ks+1] )
__device__ uint4 g_Wf[F_NCH * 8 * 2 * 32];
__device__ float g_bias[F_O];

__device__ __forceinline__ uint32_t pack2(float a, float b) {
    __half2 h = __floats2half2_rn(a, b);
    return *reinterpret_cast<uint32_t*>(&h);
}

__global__ void repack_frag_kernel(const float* __restrict__ w) {
    int idx = blockIdx.x * blockDim.x + threadIdx.x;   // 16384
    if (idx >= F_NCH * 8 * 2 * 32) return;
    int l  = idx & 31;
    int oT = (idx >> 5) & 1;
    int ks = (idx >> 6) & 7;
    int c  = idx >> 9;
    int r  = l >> 2;           // A-frag row within 8 (o low)
    int cf = l & 3;            // k-quad
    int j  = ks + 1;
    int i0 = c * 16 + 2 * cf;  // a0/a1 k positions: i0, i0+1
    int i8 = i0 + 8;           // a2/a3: i8, i8+1
    int oA = oT * 16 + r;
    int oB = oA + 8;
    uint4 v;
    v.x = pack2(w[(i0 * F_O + oA) * 9 + j], w[((i0 + 1) * F_O + oA) * 9 + j]);
    v.y = pack2(w[(i0 * F_O + oB) * 9 + j], w[((i0 + 1) * F_O + oB) * 9 + j]);
    v.z = pack2(w[(i8 * F_O + oA) * 9 + j], w[((i8 + 1) * F_O + oA) * 9 + j]);
    v.w = pack2(w[(i8 * F_O + oB) * 9 + j], w[((i8 + 1) * F_O + oB) * 9 + j]);
    g_Wf[idx] = v;
}

// Parallel bias (j=0 fold)
__global__ void bias_kernel(const float* __restrict__ w) {
    __shared__ float red[256];
    int t = threadIdx.x;
    int o = t & 31, g = t >> 5;
    float s = 0.0f;
#pragma unroll 8
    for (int i = g; i < F_I; i += 8) s += w[(i * F_O + o) * 9];
    red[t] = s;
    __syncthreads();
    if (t < 32) {
        float tot = 0.0f;
#pragma unroll
        for (int q = 0; q < 8; ++q) tot += red[q * 32 + t];
        g_bias[t] = tot;
    }
}

__device__ __forceinline__ void mma16816(float (&d)[4], const uint4& a,
                                         uint32_t b0, uint32_t b1) {
    asm volatile(
        "mma.sync.aligned.m16n8k16.row.col.f32.f16.f16.f32 "
        "{%0,%1,%2,%3}, {%4,%5,%6,%7}, {%8,%9}, {%0,%1,%2,%3};"
        : "+f"(d[0]), "+f"(d[1]), "+f"(d[2]), "+f"(d[3])
        : "r"(a.x), "r"(a.y), "r"(a.z), "r"(a.w), "r"(b0), "r"(b1));
}
// tanh(x) = 1 - 2/(exp2(2x*log2e)+1)
__device__ __forceinline__ float ftanh(float x) {
    float p;
    asm("ex2.approx.f32 %0, %1;" : "=f"(p) : "f"(x * 2.8853900817779268f));
    float r;
    asm("rcp.approx.f32 %0, %1;" : "=f"(r) : "f"(p + 1.0f));
    return fmaf(-2.0f, r, 1.0f);
}

__global__ __launch_bounds__(F_THR)
void cheby_frag_kernel(const float* __restrict__ x, float* __restrict__ out) {
    const int t    = threadIdx.x;
    const int lane = t & 31;
    const int w    = t >> 5;
    const int rowBase = blockIdx.x * (4 * F_WROWS) + w * F_WROWS;
    const int r  = lane >> 2;     // B-frag row-in-tile / A-frag o-low
    const int cf = lane & 3;

    // x pointer for tile 0; tile tl adds 8*tl rows
    const float* xp = x + (size_t)(rowBase + r) * F_I + 2 * cf;

    float acc[2][4][4];           // [oT][tile][frag]
#pragma unroll
    for (int a = 0; a < 2; ++a)
#pragma unroll
        for (int b = 0; b < 4; ++b)
#pragma unroll
            for (int q = 0; q < 4; ++q) acc[a][b][q] = 0.0f;

    const uint4* wp0 = g_Wf + lane;

    for (int c = 0; c < F_NCH; ++c) {
        const int off = c * 16;

        // ---- load this chunk's x (4 tiles x 2 LDG.64) + init recurrence ----
        float x2[4][4], up[4][4], uc[4][4];
#pragma unroll
        for (int tl = 0; tl < 4; ++tl) {
            const float* xt = xp + (size_t)(8 * tl) * F_I + off;
            float2 vA = *reinterpret_cast<const float2*>(xt);
            float2 vB = *reinterpret_cast<const float2*>(xt + 8);
            float xin[4] = {vA.x, vA.y, vB.x, vB.y};
#pragma unroll
            for (int q = 0; q < 4; ++q) {
                float th = ftanh(xin[q]);
                x2[tl][q] = th + th;
                up[tl][q] = 1.0f;       // U0 (folded into bias)
                uc[tl][q] = x2[tl][q];  // U1
            }
        }

        const uint4* wp = wp0 + c * (8 * 2 * 32);
        // ---- software-pipelined W: load ks+1 while issuing ks ----
        uint4 w0 = wp[0];
        uint4 w1 = wp[32];
#pragma unroll
        for (int ks = 0; ks < 8; ++ks) {
            uint4 n0, n1;
            if (ks < 7) {
                n0 = wp[(ks + 1) * 64];
                n1 = wp[(ks + 1) * 64 + 32];
            }
            uint32_t b0[4], b1[4];
#pragma unroll
            for (int tl = 0; tl < 4; ++tl) {
                b0[tl] = pack2(uc[tl][0], uc[tl][1]);
                b1[tl] = pack2(uc[tl][2], uc[tl][3]);
            }
#pragma unroll
            for (int tl = 0; tl < 4; ++tl) {
                mma16816(acc[0][tl], w0, b0[tl], b1[tl]);
                mma16816(acc[1][tl], w1, b0[tl], b1[tl]);
            }
            if (ks < 7) {
#pragma unroll
                for (int tl = 0; tl < 4; ++tl)
#pragma unroll
                    for (int q = 0; q < 4; ++q) {
                        float un = fmaf(x2[tl][q], uc[tl][q], -up[tl][q]);
                        up[tl][q] = uc[tl][q];
                        uc[tl][q] = un;
                    }
                w0 = n0;
                w1 = n1;
            }
        }
    }

    // ---- epilogue: C frag + bias ----
    float ba0 = g_bias[r],      bb0 = g_bias[r + 8];        // oT=0
    float ba1 = g_bias[16 + r], bb1 = g_bias[16 + r + 8];   // oT=1
#pragma unroll
    for (int tl = 0; tl < 4; ++tl) {
        int rA = rowBase + 8 * tl + 2 * cf;
        float* pA = out + (size_t)rA * F_O;
        float* pB = pA + F_O;
        pA[r]          = acc[0][tl][0] + ba0;
        pB[r]          = acc[0][tl][1] + ba0;
        pA[r + 8]      = acc[0][tl][2] + bb0;
        pB[r + 8]      = acc[0][tl][3] + bb0;
        pA[16 + r]     = acc[1][tl][0] + ba1;
        pB[16 + r]     = acc[1][tl][1] + ba1;
        pA[16 + r + 8] = acc[1][tl][2] + bb1;
        pB[16 + r + 8] = acc[1][tl][3] + bb1;
    }
}

extern "C" void kernel_launch(void* const* d_in, const int* in_sizes, int n_in,
                              void* d_out, int out_size) {
    const float* x  = (const float*)d_in[0];     // [65536, 512] f32
    const float* wc = (const float*)d_in[1];     // [512, 32, 9] f32
    float* out = (float*)d_out;                  // [65536, 32] f32

    int Brows = in_sizes[0] / F_I;               // 65536

    repack_frag_kernel<<<(F_NCH * 8 * 2 * 32 + 255) / 256, 256>>>(wc);
    bias_kernel<<<1, 256>>>(wc);

    cheby_frag_kernel<<<Brows / (4 * F_WROWS), F_THR>>>(x, out);
}

// round 13
// speedup vs baseline: 1.1895x; 1.1895x over previous
#include <cuda_runtime.h>
#include <cuda_fp16.h>
#include <stdint.h>

// Problem constants
#define F_I     512
#define F_O     32
#define F_NCH   32                 // i-chunks of 16
#define F_WROWS 16                 // rows per warp
#define F_THR   128                // 4 warps -> 64 rows per CTA

// W packed in exact mma A-fragment order:
//   g_Wf[ ((c*8 + ks)*2 + oT)*32 + lane ] = uint4{a0,a1,a2,a3}
//   A[rr][kk] = fp16( W[i = c*16+kk][o = oT*16+rr][j = ks+1] )
__device__ uint4 g_Wf[F_NCH * 8 * 2 * 32];
__device__ float g_bias[F_O];

__device__ __forceinline__ uint32_t pack2(float a, float b) {
    __half2 h = __floats2half2_rn(a, b);
    return *reinterpret_cast<uint32_t*>(&h);
}

// Fused prep: blocks 0..63 repack W fragments; block 64 computes bias.
__global__ void prep_kernel(const float* __restrict__ w) {
    if (blockIdx.x < 64) {
        int idx = blockIdx.x * 256 + threadIdx.x;      // 16384
        int l  = idx & 31;
        int oT = (idx >> 5) & 1;
        int ks = (idx >> 6) & 7;
        int c  = idx >> 9;
        int r  = l >> 2;           // A-frag row within 8 (o low)
        int cf = l & 3;            // k-quad
        int j  = ks + 1;
        int i0 = c * 16 + 2 * cf;  // a0/a1 k positions: i0, i0+1
        int i8 = i0 + 8;           // a2/a3: i8, i8+1
        int oA = oT * 16 + r;
        int oB = oA + 8;
        uint4 v;
        v.x = pack2(w[(i0 * F_O + oA) * 9 + j], w[((i0 + 1) * F_O + oA) * 9 + j]);
        v.y = pack2(w[(i0 * F_O + oB) * 9 + j], w[((i0 + 1) * F_O + oB) * 9 + j]);
        v.z = pack2(w[(i8 * F_O + oA) * 9 + j], w[((i8 + 1) * F_O + oA) * 9 + j]);
        v.w = pack2(w[(i8 * F_O + oB) * 9 + j], w[((i8 + 1) * F_O + oB) * 9 + j]);
        g_Wf[idx] = v;
    } else {
        // bias: sum of j=0 plane over i, per output o
        __shared__ float red[256];
        int t = threadIdx.x;
        int o = t & 31, g = t >> 5;
        float s = 0.0f;
#pragma unroll 8
        for (int i = g; i < F_I; i += 8) s += w[(i * F_O + o) * 9];
        red[t] = s;
        __syncthreads();
        if (t < 32) {
            float tot = 0.0f;
#pragma unroll
            for (int q = 0; q < 8; ++q) tot += red[q * 32 + t];
            g_bias[t] = tot;
        }
    }
}

__device__ __forceinline__ void mma16816(float (&d)[4], const uint32_t (&a)[4],
                                         uint32_t b0, uint32_t b1) {
    asm volatile(
        "mma.sync.aligned.m16n8k16.row.col.f32.f16.f16.f32 "
        "{%0,%1,%2,%3}, {%4,%5,%6,%7}, {%8,%9}, {%0,%1,%2,%3};"
        : "+f"(d[0]), "+f"(d[1]), "+f"(d[2]), "+f"(d[3])
        : "r"(a[0]), "r"(a[1]), "r"(a[2]), "r"(a[3]), "r"(b0), "r"(b1));
}
// tanh(x) = 1 - 2/(exp2(2x*log2e)+1)
__device__ __forceinline__ float ftanh(float x) {
    float p;
    asm("ex2.approx.f32 %0, %1;" : "=f"(p) : "f"(x * 2.8853900817779268f));
    float r;
    asm("rcp.approx.f32 %0, %1;" : "=f"(r) : "f"(p + 1.0f));
    return fmaf(-2.0f, r, 1.0f);
}

__global__ __launch_bounds__(F_THR, 5)
void cheby_frag_kernel(const float* __restrict__ x, float* __restrict__ out) {
    const int t    = threadIdx.x;
    const int lane = t & 31;
    const int w    = t >> 5;
    const int rowBase = blockIdx.x * (4 * F_WROWS) + w * F_WROWS;
    const int r  = lane >> 2;     // B-frag row-in-tile / A-frag o-low
    const int cf = lane & 3;

    // x pointers: tile 0 row = rowBase + r, tile 1 row = rowBase + 8 + r
    const float* xp0 = x + (size_t)(rowBase + r) * F_I + 2 * cf;
    const float* xp1 = x + (size_t)(rowBase + 8 + r) * F_I + 2 * cf;

    float acc[2][2][4];           // [oT][tile][frag]
#pragma unroll
    for (int a = 0; a < 2; ++a)
#pragma unroll
        for (int b = 0; b < 2; ++b)
#pragma unroll
            for (int q = 0; q < 4; ++q) acc[a][b][q] = 0.0f;

    const uint4* wp0 = g_Wf + lane;

    // ---- prefetch chunk 0's x into registers ----
    float2 vA0 = *reinterpret_cast<const float2*>(xp0);
    float2 vB0 = *reinterpret_cast<const float2*>(xp0 + 8);
    float2 vA1 = *reinterpret_cast<const float2*>(xp1);
    float2 vB1 = *reinterpret_cast<const float2*>(xp1 + 8);

    for (int c = 0; c < F_NCH; ++c) {
        // ---- init recurrence from prefetched x (consumes v*) ----
        float x2[2][4], up[2][4], uc[2][4];
        {
            float xin[2][4] = {{vA0.x, vA0.y, vB0.x, vB0.y},
                               {vA1.x, vA1.y, vB1.x, vB1.y}};
#pragma unroll
            for (int tl = 0; tl < 2; ++tl)
#pragma unroll
                for (int q = 0; q < 4; ++q) {
                    float th = ftanh(xin[tl][q]);
                    x2[tl][q] = th + th;
                    up[tl][q] = 1.0f;       // U0 (folded into bias)
                    uc[tl][q] = x2[tl][q];  // U1
                }
        }

        // ---- issue next chunk's x loads NOW; latency hides under ks loop ----
        if (c + 1 < F_NCH) {
            const int off = (c + 1) * 16;
            vA0 = *reinterpret_cast<const float2*>(xp0 + off);
            vB0 = *reinterpret_cast<const float2*>(xp0 + off + 8);
            vA1 = *reinterpret_cast<const float2*>(xp1 + off);
            vB1 = *reinterpret_cast<const float2*>(xp1 + off + 8);
        }

        const uint4* wp = wp0 + c * (8 * 2 * 32);
#pragma unroll
        for (int ks = 0; ks < 8; ++ks) {
            uint4 w0 = wp[0];
            uint4 w1 = wp[32];
            wp += 64;
            uint32_t a0[4] = {w0.x, w0.y, w0.z, w0.w};
            uint32_t a1[4] = {w1.x, w1.y, w1.z, w1.w};
#pragma unroll
            for (int tl = 0; tl < 2; ++tl) {
                uint32_t b0 = pack2(uc[tl][0], uc[tl][1]);
                uint32_t b1 = pack2(uc[tl][2], uc[tl][3]);
                mma16816(acc[0][tl], a0, b0, b1);
                mma16816(acc[1][tl], a1, b0, b1);
            }
            if (ks < 7) {
#pragma unroll
                for (int tl = 0; tl < 2; ++tl)
#pragma unroll
                    for (int q = 0; q < 4; ++q) {
                        float un = fmaf(x2[tl][q], uc[tl][q], -up[tl][q]);
                        up[tl][q] = uc[tl][q];
                        uc[tl][q] = un;
                    }
            }
        }
    }

    // ---- epilogue: C frag (m = o, n = batch row) + bias ----
    float b0a = g_bias[r],      b0b = g_bias[r + 8];        // oT=0
    float b1a = g_bias[16 + r], b1b = g_bias[16 + r + 8];   // oT=1
#pragma unroll
    for (int tl = 0; tl < 2; ++tl) {
        int rA = rowBase + 8 * tl + 2 * cf;
        float* pA = out + (size_t)rA * F_O;
        float* pB = pA + F_O;
        pA[r]          = acc[0][tl][0] + b0a;
        pB[r]          = acc[0][tl][1] + b0a;
        pA[r + 8]      = acc[0][tl][2] + b0b;
        pB[r + 8]      = acc[0][tl][3] + b0b;
        pA[16 + r]     = acc[1][tl][0] + b1a;
        pB[16 + r]     = acc[1][tl][1] + b1a;
        pA[16 + r + 8] = acc[1][tl][2] + b1b;
        pB[16 + r + 8] = acc[1][tl][3] + b1b;
    }
}

extern "C" void kernel_launch(void* const* d_in, const int* in_sizes, int n_in,
                              void* d_out, int out_size) {
    const float* x  = (const float*)d_in[0];     // [65536, 512] f32
    const float* wc = (const float*)d_in[1];     // [512, 32, 9] f32
    float* out = (float*)d_out;                  // [65536, 32] f32

    int Brows = in_sizes[0] / F_I;               // 65536

    prep_kernel<<<65, 256>>>(wc);                // repack (blocks 0-63) + bias (block 64)

    cheby_frag_kernel<<<Brows / 64, F_THR>>>(x, out);
}